// round 1
// baseline (speedup 1.0000x reference)
#include <cuda_runtime.h>
#include <cuda_bf16.h>
#include <math.h>

// Problem constants
#define TT 2048      // tokens (B*S)
#define HH 768       // hidden
#define II 1536      // intermediate
#define EE 8         // experts
#define KK 2         // top-k
#define CAP 768      // capacity = max(8, int((T*K//E)*1.5)) = 768

// ---------------- scratch (device globals; allocation-free) ----------------
__device__ float g_importance[EE];        // sum of gate_probs per expert
__device__ int   g_topk_idx[TT * KK];     // expert id per (t,k)
__device__ float g_topk_w[TT * KK];       // normalized clipped weight per (t,k)
__device__ int   g_slot[TT * KK];         // slot within expert list, -1 if dropped
__device__ int   g_list[EE * (KK * CAP)]; // token id per (e, slot)
__device__ int   g_cnt[KK * EE];          // kept count per (k,e)
__device__ int   g_keptcnt[EE];           // kept per expert (both k)
__device__ float g_dropped;               // total dropped assignments
__device__ float g_hbuf[EE * (KK * CAP) * II];  // SwiGLU intermediate (~75MB)
__device__ float g_ybuf[EE * (KK * CAP) * HH];  // expert outputs (~38MB)

// ---------------- zero importance ----------------
__global__ void zero_kernel() {
    if (threadIdx.x < EE) g_importance[threadIdx.x] = 0.0f;
}

// ---------------- routing: logits, softmax, top-2 ----------------
__global__ void routing_kernel(const float* __restrict__ x,
                               const float* __restrict__ wg) {
    int t = blockIdx.x;
    __shared__ float sx[HH];
    __shared__ float slog[EE];
    int tid = threadIdx.x;                 // 256 threads, 8 warps
    for (int i = tid; i < HH; i += 256) sx[i] = x[t * HH + i];
    __syncthreads();
    int warp = tid >> 5, lane = tid & 31;
    float sum = 0.0f;
    for (int j = lane; j < HH; j += 32) sum += sx[j] * wg[j * EE + warp];
    for (int o = 16; o; o >>= 1) sum += __shfl_xor_sync(0xffffffffu, sum, o);
    if (lane == 0) slog[warp] = sum;
    __syncthreads();
    if (tid == 0) {
        float mx = slog[0];
        for (int e = 1; e < EE; e++) mx = fmaxf(mx, slog[e]);
        float p[EE], s = 0.0f;
        for (int e = 0; e < EE; e++) { p[e] = expf(slog[e] - mx); s += p[e]; }
        for (int e = 0; e < EE; e++) p[e] /= s;
        // top-2 (lower index wins ties, matching jax top_k)
        int e0 = 0;
        for (int e = 1; e < EE; e++) if (p[e] > p[e0]) e0 = e;
        int e1 = -1;
        for (int e = 0; e < EE; e++) {
            if (e == e0) continue;
            if (e1 < 0 || p[e] > p[e1]) e1 = e;
        }
        float ps = p[e0] + p[e1] + 1e-8f;
        float w0 = fminf(fmaxf(p[e0] / ps, 1e-8f), 10.0f);
        float w1 = fminf(fmaxf(p[e1] / ps, 1e-8f), 10.0f);
        g_topk_idx[t * 2 + 0] = e0;
        g_topk_idx[t * 2 + 1] = e1;
        g_topk_w[t * 2 + 0] = w0;
        g_topk_w[t * 2 + 1] = w1;
        for (int e = 0; e < EE; e++) atomicAdd(&g_importance[e], p[e]);
    }
}

// ---------------- scan: exact token-order ranks + capacity drop ----------------
// single block, 1024 threads; matches jnp.cumsum(onehot, axis=0) semantics.
__global__ void scan_kernel() {
    __shared__ int warp_cnt[32][EE];
    __shared__ int warp_pref[32][EE];
    __shared__ int running[EE];
    __shared__ int chunk_tot[EE];
    __shared__ int tot[KK][EE];
    int tid = threadIdx.x, lane = tid & 31, warp = tid >> 5;

    for (int k = 0; k < KK; k++) {
        if (tid < EE) running[tid] = 0;
        __syncthreads();
        for (int chunk = 0; chunk < TT / 1024; chunk++) {
            int t = chunk * 1024 + tid;
            int e = g_topk_idx[t * 2 + k];
            unsigned mask = __match_any_sync(0xffffffffu, e);
            int lane_pref = __popc(mask & ((1u << lane) - 1));
            int warp_total = __popc(mask);
            if (tid < 32 * EE) warp_cnt[tid / EE][tid % EE] = 0;
            __syncthreads();
            if (lane_pref == 0) warp_cnt[warp][e] = warp_total;
            __syncthreads();
            if (tid < 32 * EE) {
                int w = tid / EE, ee = tid % EE;
                int p = 0;
                for (int ww = 0; ww < w; ww++) p += warp_cnt[ww][ee];
                warp_pref[w][ee] = p;
                if (w == 31) chunk_tot[ee] = p + warp_cnt[31][ee];
            }
            __syncthreads();
            int rank = running[e] + warp_pref[warp][e] + lane_pref + 1; // 1-based inclusive
            bool kept = (rank <= CAP);
            int slot = kept ? (k * CAP + rank - 1) : -1;
            g_slot[t * 2 + k] = slot;
            if (kept) g_list[e * (KK * CAP) + slot] = t;
            __syncthreads();
            if (tid < EE) running[tid] += chunk_tot[tid];
            __syncthreads();
        }
        if (tid < EE) tot[k][tid] = running[tid];
        __syncthreads();
    }
    if (tid == 0) {
        int drop = 0;
        for (int e = 0; e < EE; e++) {
            int c0 = min(tot[0][e], CAP), c1 = min(tot[1][e], CAP);
            g_cnt[0 * EE + e] = c0;
            g_cnt[1 * EE + e] = c1;
            g_keptcnt[e] = c0 + c1;
            drop += (tot[0][e] - c0) + (tot[1][e] - c1);
        }
        g_dropped = (float)drop;
    }
}

// ---------------- GEMM1: h = silu(X@w1) * (X@w3), gathered rows ----------------
// grid: (II/64, KK*CAP/64, EE), 256 threads, 4x4 per thread, TK=16
__global__ void __launch_bounds__(256) gemm1_kernel(const float* __restrict__ x,
                                                    const float* __restrict__ w1,
                                                    const float* __restrict__ w3) {
    int e = blockIdx.z;
    int by = blockIdx.y;                      // slot tile (0..23); 0..11 -> k=0, 12..23 -> k=1
    int bx = blockIdx.x;                      // I tile (0..23)
    int kslot = (by < CAP / 64) ? 0 : 1;
    int cnt = g_cnt[kslot * EE + e];
    int tile_in_k = (by - kslot * (CAP / 64)) * 64;
    if (tile_in_k >= cnt) return;
    int slot0 = by * 64;

    __shared__ float As[64][17];
    __shared__ float B1s[16][64];
    __shared__ float B3s[16][64];
    __shared__ int stok[64];
    int tid = threadIdx.x;

    if (tid < 64) {
        bool valid = (tile_in_k + tid) < cnt;
        stok[tid] = valid ? g_list[e * (KK * CAP) + slot0 + tid] : -1;
    }
    __syncthreads();

    float accG[4][4] = {}, accU[4][4] = {};
    int ty = tid >> 4, tx = tid & 15;
    const float* w1b = w1 + (size_t)e * HH * II;
    const float* w3b = w3 + (size_t)e * HH * II;

    int arow = tid >> 2, ac4 = tid & 3;
    int brow = tid >> 4, bc4 = tid & 15;

    for (int k0 = 0; k0 < HH; k0 += 16) {
        int tok = stok[arow];
        float4 v = make_float4(0.f, 0.f, 0.f, 0.f);
        if (tok >= 0) v = *(const float4*)(x + (size_t)tok * HH + k0 + ac4 * 4);
        As[arow][ac4 * 4 + 0] = v.x; As[arow][ac4 * 4 + 1] = v.y;
        As[arow][ac4 * 4 + 2] = v.z; As[arow][ac4 * 4 + 3] = v.w;

        *(float4*)&B1s[brow][bc4 * 4] = *(const float4*)(w1b + (size_t)(k0 + brow) * II + bx * 64 + bc4 * 4);
        *(float4*)&B3s[brow][bc4 * 4] = *(const float4*)(w3b + (size_t)(k0 + brow) * II + bx * 64 + bc4 * 4);
        __syncthreads();

#pragma unroll
        for (int kk = 0; kk < 16; kk++) {
            float a[4], b1[4], b3[4];
#pragma unroll
            for (int i = 0; i < 4; i++) a[i] = As[ty * 4 + i][kk];
            *(float4*)b1 = *(float4*)&B1s[kk][tx * 4];
            *(float4*)b3 = *(float4*)&B3s[kk][tx * 4];
#pragma unroll
            for (int i = 0; i < 4; i++)
#pragma unroll
                for (int j = 0; j < 4; j++) {
                    accG[i][j] += a[i] * b1[j];
                    accU[i][j] += a[i] * b3[j];
                }
        }
        __syncthreads();
    }

#pragma unroll
    for (int i = 0; i < 4; i++) {
        if (tile_in_k + ty * 4 + i >= cnt) continue;
        int s = slot0 + ty * 4 + i;
        float* hrow = &g_hbuf[((size_t)e * (KK * CAP) + s) * II];
        float4 o;
        float g0 = accG[i][0], g1 = accG[i][1], g2 = accG[i][2], g3 = accG[i][3];
        o.x = g0 / (1.f + expf(-g0)) * accU[i][0];
        o.y = g1 / (1.f + expf(-g1)) * accU[i][1];
        o.z = g2 / (1.f + expf(-g2)) * accU[i][2];
        o.w = g3 / (1.f + expf(-g3)) * accU[i][3];
        *(float4*)&hrow[bx * 64 + tx * 4] = o;
    }
}

// ---------------- GEMM2: y = h @ w2 ----------------
// grid: (HH/64, KK*CAP/64, EE)
__global__ void __launch_bounds__(256) gemm2_kernel(const float* __restrict__ w2) {
    int e = blockIdx.z;
    int by = blockIdx.y;
    int bx = blockIdx.x;
    int kslot = (by < CAP / 64) ? 0 : 1;
    int cnt = g_cnt[kslot * EE + e];
    int tile_in_k = (by - kslot * (CAP / 64)) * 64;
    if (tile_in_k >= cnt) return;
    int slot0 = by * 64;

    __shared__ float As[64][17];
    __shared__ float Bs[16][64];
    int tid = threadIdx.x;
    float acc[4][4] = {};
    int ty = tid >> 4, tx = tid & 15;
    const float* w2b = w2 + (size_t)e * II * HH;

    int arow = tid >> 2, ac4 = tid & 3;
    int brow = tid >> 4, bc4 = tid & 15;

    for (int k0 = 0; k0 < II; k0 += 16) {
        float4 v = make_float4(0.f, 0.f, 0.f, 0.f);
        if (tile_in_k + arow < cnt)
            v = *(const float4*)&g_hbuf[((size_t)e * (KK * CAP) + slot0 + arow) * II + k0 + ac4 * 4];
        As[arow][ac4 * 4 + 0] = v.x; As[arow][ac4 * 4 + 1] = v.y;
        As[arow][ac4 * 4 + 2] = v.z; As[arow][ac4 * 4 + 3] = v.w;

        *(float4*)&Bs[brow][bc4 * 4] = *(const float4*)(w2b + (size_t)(k0 + brow) * HH + bx * 64 + bc4 * 4);
        __syncthreads();

#pragma unroll
        for (int kk = 0; kk < 16; kk++) {
            float a[4], b[4];
#pragma unroll
            for (int i = 0; i < 4; i++) a[i] = As[ty * 4 + i][kk];
            *(float4*)b = *(float4*)&Bs[kk][tx * 4];
#pragma unroll
            for (int i = 0; i < 4; i++)
#pragma unroll
                for (int j = 0; j < 4; j++) acc[i][j] += a[i] * b[j];
        }
        __syncthreads();
    }

#pragma unroll
    for (int i = 0; i < 4; i++) {
        if (tile_in_k + ty * 4 + i >= cnt) continue;
        int s = slot0 + ty * 4 + i;
        *(float4*)&g_ybuf[((size_t)e * (KK * CAP) + s) * HH + bx * 64 + tx * 4] =
            make_float4(acc[i][0], acc[i][1], acc[i][2], acc[i][3]);
    }
}

// ---------------- combine: out[t] = sum_k w * y ----------------
__global__ void combine_kernel(float* __restrict__ out) {
    int t = blockIdx.x;
    __shared__ int se[2], ss[2];
    __shared__ float sw[2];
    if (threadIdx.x < 2) {
        se[threadIdx.x] = g_topk_idx[t * 2 + threadIdx.x];
        ss[threadIdx.x] = g_slot[t * 2 + threadIdx.x];
        sw[threadIdx.x] = g_topk_w[t * 2 + threadIdx.x];
    }
    __syncthreads();
    for (int h = threadIdx.x; h < HH; h += 256) {
        float v = 0.0f;
        if (ss[0] >= 0) v += sw[0] * g_ybuf[((size_t)se[0] * (KK * CAP) + ss[0]) * HH + h];
        if (ss[1] >= 0) v += sw[1] * g_ybuf[((size_t)se[1] * (KK * CAP) + ss[1]) * HH + h];
        out[(size_t)t * HH + h] = v;
    }
}

// ---------------- aux loss scalar ----------------
__global__ void aux_kernel(float* __restrict__ out, int out_size) {
    if (out_size < TT * HH + 1) return;
    float a = 0.0f;
    for (int e = 0; e < EE; e++) {
        float usage = (float)g_keptcnt[e] / (float)(TT * KK);
        float imp = g_importance[e] / (float)TT;
        a += usage * imp;
    }
    a *= (float)EE;
    if (g_dropped > 0.0f) a += g_dropped / (float)TT * 0.1f;
    a = fminf(a, 1.0f) * 0.001f;
    out[TT * HH] = a;
}

// ---------------- launch ----------------
extern "C" void kernel_launch(void* const* d_in, const int* in_sizes, int n_in,
                              void* d_out, int out_size) {
    const float* x      = (const float*)d_in[0]; // [B,S,H] = [T,H]
    const float* w_gate = (const float*)d_in[1]; // [H,E]
    const float* w1     = (const float*)d_in[2]; // [E,H,I]
    const float* w3     = (const float*)d_in[3]; // [E,H,I]
    const float* w2     = (const float*)d_in[4]; // [E,I,H]
    float* out = (float*)d_out;

    zero_kernel<<<1, 32>>>();
    routing_kernel<<<TT, 256>>>(x, w_gate);
    scan_kernel<<<1, 1024>>>();
    gemm1_kernel<<<dim3(II / 64, KK * CAP / 64, EE), 256>>>(x, w1, w3);
    gemm2_kernel<<<dim3(HH / 64, KK * CAP / 64, EE), 256>>>(w2);
    combine_kernel<<<TT, 256>>>(out);
    aux_kernel<<<1, 1>>>(out, out_size);
}

// round 4
// speedup vs baseline: 2.4429x; 2.4429x over previous
#include <cuda_runtime.h>
#include <cuda_bf16.h>
#include <stdint.h>
#include <math.h>

// Problem constants
#define TT 2048      // tokens (B*S)
#define HH 768       // hidden
#define II 1536      // intermediate
#define EE 8         // experts
#define KK 2         // top-k
#define CAP 768      // capacity
#define SLOTS (KK*CAP)   // 1536 slot rows per expert

// ---------------- scratch (device globals; allocation-free) ----------------
__device__ float g_importance[EE];
__device__ int   g_topk_idx[TT * KK];
__device__ float g_topk_w[TT * KK];
__device__ int   g_slot[TT * KK];
__device__ int   g_list[EE * SLOTS];
__device__ int   g_cnt[KK * EE];
__device__ int   g_keptcnt[EE];
__device__ float g_dropped;
__device__ float g_hbuf[EE * SLOTS * II];        // SwiGLU intermediate (~75MB)
__device__ float g_ybuf[EE * SLOTS * HH];        // expert outputs    (~38MB)

// ---------------- PTX helpers ----------------
__device__ __forceinline__ uint32_t s2u(const void* p) {
    uint32_t a;
    asm("{ .reg .u64 t; cvta.to.shared.u64 t, %1; cvt.u32.u64 %0, t; }" : "=r"(a) : "l"(p));
    return a;
}
__device__ __forceinline__ void cpa16(uint32_t dst, const void* src) {
    asm volatile("cp.async.cg.shared.global [%0], [%1], 16;" :: "r"(dst), "l"(src));
}
__device__ __forceinline__ void cpa_commit() { asm volatile("cp.async.commit_group;" ::: "memory"); }
template<int N> __device__ __forceinline__ void cpa_wait() {
    asm volatile("cp.async.wait_group %0;" :: "n"(N) : "memory");
}
__device__ __forceinline__ uint32_t f2tf(float f) {
    uint32_t r; asm("cvt.rna.tf32.f32 %0, %1;" : "=r"(r) : "f"(f)); return r;
}
__device__ __forceinline__ void mma8(float* d, const uint32_t* a, const uint32_t* b) {
    asm volatile(
        "mma.sync.aligned.m16n8k8.row.col.f32.tf32.tf32.f32 "
        "{%0,%1,%2,%3}, {%4,%5,%6,%7}, {%8,%9}, {%0,%1,%2,%3};"
        : "+f"(d[0]), "+f"(d[1]), "+f"(d[2]), "+f"(d[3])
        : "r"(a[0]), "r"(a[1]), "r"(a[2]), "r"(a[3]), "r"(b[0]), "r"(b[1]));
}

// ---------------- zero ----------------
__global__ void zero_kernel() {
    if (threadIdx.x < EE) g_importance[threadIdx.x] = 0.0f;
}

// ---------------- routing ----------------
__global__ void routing_kernel(const float* __restrict__ x,
                               const float* __restrict__ wg) {
    int t = blockIdx.x;
    __shared__ float sx[HH];
    __shared__ float slog[EE];
    int tid = threadIdx.x;
    for (int i = tid; i < HH; i += 256) sx[i] = x[t * HH + i];
    __syncthreads();
    int warp = tid >> 5, lane = tid & 31;
    float sum = 0.0f;
    for (int j = lane; j < HH; j += 32) sum += sx[j] * wg[j * EE + warp];
    for (int o = 16; o; o >>= 1) sum += __shfl_xor_sync(0xffffffffu, sum, o);
    if (lane == 0) slog[warp] = sum;
    __syncthreads();
    if (tid == 0) {
        float mx = slog[0];
        for (int e = 1; e < EE; e++) mx = fmaxf(mx, slog[e]);
        float p[EE], s = 0.0f;
        for (int e = 0; e < EE; e++) { p[e] = expf(slog[e] - mx); s += p[e]; }
        for (int e = 0; e < EE; e++) p[e] /= s;
        int e0 = 0;
        for (int e = 1; e < EE; e++) if (p[e] > p[e0]) e0 = e;
        int e1 = -1;
        for (int e = 0; e < EE; e++) {
            if (e == e0) continue;
            if (e1 < 0 || p[e] > p[e1]) e1 = e;
        }
        float ps = p[e0] + p[e1] + 1e-8f;
        float w0 = fminf(fmaxf(p[e0] / ps, 1e-8f), 10.0f);
        float w1 = fminf(fmaxf(p[e1] / ps, 1e-8f), 10.0f);
        g_topk_idx[t * 2 + 0] = e0;
        g_topk_idx[t * 2 + 1] = e1;
        g_topk_w[t * 2 + 0] = w0;
        g_topk_w[t * 2 + 1] = w1;
        for (int e = 0; e < EE; e++) atomicAdd(&g_importance[e], p[e]);
    }
}

// ---------------- scan ----------------
__global__ void scan_kernel() {
    __shared__ int warp_cnt[32][EE];
    __shared__ int warp_pref[32][EE];
    __shared__ int running[EE];
    __shared__ int chunk_tot[EE];
    __shared__ int tot[KK][EE];
    int tid = threadIdx.x, lane = tid & 31, warp = tid >> 5;

    for (int k = 0; k < KK; k++) {
        if (tid < EE) running[tid] = 0;
        __syncthreads();
        for (int chunk = 0; chunk < TT / 1024; chunk++) {
            int t = chunk * 1024 + tid;
            int e = g_topk_idx[t * 2 + k];
            unsigned mask = __match_any_sync(0xffffffffu, e);
            int lane_pref = __popc(mask & ((1u << lane) - 1));
            int warp_total = __popc(mask);
            if (tid < 32 * EE) warp_cnt[tid / EE][tid % EE] = 0;
            __syncthreads();
            if (lane_pref == 0) warp_cnt[warp][e] = warp_total;
            __syncthreads();
            if (tid < 32 * EE) {
                int w = tid / EE, ee = tid % EE;
                int p = 0;
                for (int ww = 0; ww < w; ww++) p += warp_cnt[ww][ee];
                warp_pref[w][ee] = p;
                if (w == 31) chunk_tot[ee] = p + warp_cnt[31][ee];
            }
            __syncthreads();
            int rank = running[e] + warp_pref[warp][e] + lane_pref + 1;
            bool kept = (rank <= CAP);
            int slot = kept ? (k * CAP + rank - 1) : -1;
            g_slot[t * 2 + k] = slot;
            if (kept) g_list[e * SLOTS + slot] = t;
            __syncthreads();
            if (tid < EE) running[tid] += chunk_tot[tid];
            __syncthreads();
        }
        if (tid < EE) tot[k][tid] = running[tid];
        __syncthreads();
    }
    if (tid == 0) {
        int drop = 0;
        for (int e = 0; e < EE; e++) {
            int c0 = min(tot[0][e], CAP), c1 = min(tot[1][e], CAP);
            g_cnt[0 * EE + e] = c0;
            g_cnt[1 * EE + e] = c1;
            g_keptcnt[e] = c0 + c1;
            drop += (tot[0][e] - c0) + (tot[1][e] - c1);
        }
        g_dropped = (float)drop;
    }
}

// ================ GEMM1: mma.sync tf32, fused SwiGLU ================
// CTA: M=128 slots x N=256 (128 w1-cols + 128 w3-cols). 512 threads, 16 warps.
// warpM = w>>3 (2), warpN = w&7 (8). Warp: 64 rows x (16 G-cols + 16 U-cols).
// SMEM floats: As[2][128*36], Bs[2][32*264], stok[128]
#define APITCH 36
#define BPITCH 264
#define G1_SMEM ((2*128*APITCH + 2*32*BPITCH) * 4 + 512)
__global__ void __launch_bounds__(512, 1) gemm1_mma(const float* __restrict__ x,
                                                    const float* __restrict__ w1,
                                                    const float* __restrict__ w3) {
    extern __shared__ float s[];
    float* As = s;                        // 2 x 4608
    float* Bs = s + 2 * 128 * APITCH;     // 2 x 8448
    int* stok = (int*)(Bs + 2 * 32 * BPITCH);

    int e = blockIdx.z, by = blockIdx.y, bx = blockIdx.x;
    int kslot = (by >= 6) ? 1 : 0;
    int cnt = g_cnt[kslot * EE + e];
    int tile0 = (by - kslot * 6) * 128;
    if (tile0 >= cnt) return;
    int valid = min(128, cnt - tile0);
    int slot0 = by * 128;
    int tid = threadIdx.x;
    int lane = tid & 31, w = tid >> 5;
    int warpM = w >> 3, warpN = w & 7;

    if (tid < 128)
        stok[tid] = (tid < valid) ? g_list[e * SLOTS + slot0 + tid]
                                  : g_list[e * SLOTS + slot0];
    __syncthreads();

    const float* w1b = w1 + (size_t)e * HH * II + bx * 128;
    const float* w3b = w3 + (size_t)e * HH * II + bx * 128;

    auto fill = [&](int buf, int c) {
        uint32_t au = s2u(As + buf * 128 * APITCH);
        uint32_t bu_ = s2u(Bs + buf * 32 * BPITCH);
        int k0 = c * 32;
#pragma unroll
        for (int i = tid; i < 1024; i += 512) {
            int row = i >> 3, seg = i & 7;
            cpa16(au + (uint32_t)(row * APITCH + seg * 4) * 4,
                  x + (size_t)stok[row] * HH + k0 + seg * 4);
        }
#pragma unroll
        for (int i = tid; i < 2048; i += 512) {
            int k = i >> 6, seg = i & 63;
            const float* src = (seg < 32) ? (w1b + (size_t)(k0 + k) * II + seg * 4)
                                          : (w3b + (size_t)(k0 + k) * II + (seg - 32) * 4);
            int dc = (seg < 32) ? seg * 4 : 128 + (seg - 32) * 4;
            cpa16(bu_ + (uint32_t)(k * BPITCH + dc) * 4, src);
        }
    };

    fill(0, 0); cpa_commit();
    float accG[4][2][4] = {}, accU[4][2][4] = {};
    const int NC = HH / 32; // 24
    for (int c = 0; c < NC; c++) {
        int b = c & 1;
        if (c + 1 < NC) { fill(b ^ 1, c + 1); cpa_commit(); cpa_wait<1>(); }
        else { cpa_wait<0>(); }
        __syncthreads();
        const float* A = As + b * 128 * APITCH;
        const float* B = Bs + b * 32 * BPITCH;
#pragma unroll
        for (int ks = 0; ks < 4; ks++) {
            int kc = ks * 8 + (lane & 3);
            int r0 = warpM * 64 + (lane >> 2);
            uint32_t af[4][4];
#pragma unroll
            for (int mf = 0; mf < 4; mf++) {
                int r = r0 + mf * 16;
                af[mf][0] = f2tf(A[r * APITCH + kc]);
                af[mf][1] = f2tf(A[(r + 8) * APITCH + kc]);
                af[mf][2] = f2tf(A[r * APITCH + kc + 4]);
                af[mf][3] = f2tf(A[(r + 8) * APITCH + kc + 4]);
            }
            int bn = warpN * 16 + (lane >> 2);
            uint32_t bg[2][2], bu2[2][2];
#pragma unroll
            for (int nf = 0; nf < 2; nf++) {
                bg[nf][0]  = f2tf(B[kc * BPITCH + bn + nf * 8]);
                bg[nf][1]  = f2tf(B[(kc + 4) * BPITCH + bn + nf * 8]);
                bu2[nf][0] = f2tf(B[kc * BPITCH + 128 + bn + nf * 8]);
                bu2[nf][1] = f2tf(B[(kc + 4) * BPITCH + 128 + bn + nf * 8]);
            }
#pragma unroll
            for (int mf = 0; mf < 4; mf++)
#pragma unroll
                for (int nf = 0; nf < 2; nf++) {
                    mma8(accG[mf][nf], af[mf], bg[nf]);
                    mma8(accU[mf][nf], af[mf], bu2[nf]);
                }
        }
        __syncthreads();
    }

    // epilogue: SwiGLU, write hbuf
#pragma unroll
    for (int mf = 0; mf < 4; mf++) {
        int rbase = warpM * 64 + mf * 16 + (lane >> 2);
#pragma unroll
        for (int nf = 0; nf < 2; nf++) {
            int col = bx * 128 + warpN * 16 + nf * 8 + 2 * (lane & 3);
#pragma unroll
            for (int h = 0; h < 2; h++) {
                int r = rbase + h * 8;
                if (r < valid) {
                    float g0 = accG[mf][nf][h * 2 + 0], g1 = accG[mf][nf][h * 2 + 1];
                    float u0 = accU[mf][nf][h * 2 + 0], u1 = accU[mf][nf][h * 2 + 1];
                    float2 o;
                    o.x = g0 / (1.0f + expf(-g0)) * u0;
                    o.y = g1 / (1.0f + expf(-g1)) * u1;
                    *(float2*)&g_hbuf[((size_t)e * SLOTS + slot0 + r) * II + col] = o;
                }
            }
        }
    }
}

// ================ GEMM2: mma.sync tf32 ================
// CTA: M=128 slots x N=256 H-cols. 512 threads. warp: 64 x 32.
#define G2_SMEM ((2*128*APITCH + 2*32*BPITCH) * 4)
__global__ void __launch_bounds__(512, 1) gemm2_mma(const float* __restrict__ w2) {
    extern __shared__ float s[];
    float* As = s;
    float* Bs = s + 2 * 128 * APITCH;

    int e = blockIdx.z, by = blockIdx.y, bx = blockIdx.x; // bx 0..2
    int kslot = (by >= 6) ? 1 : 0;
    int cnt = g_cnt[kslot * EE + e];
    int tile0 = (by - kslot * 6) * 128;
    if (tile0 >= cnt) return;
    int valid = min(128, cnt - tile0);
    int slot0 = by * 128;
    int tid = threadIdx.x;
    int lane = tid & 31, w = tid >> 5;
    int warpM = w >> 3, warpN = w & 7;

    const float* Ab = g_hbuf + ((size_t)e * SLOTS + slot0) * II;
    const float* Bb = w2 + (size_t)e * II * HH + bx * 256;

    auto fill = [&](int buf, int c) {
        uint32_t au = s2u(As + buf * 128 * APITCH);
        uint32_t bu_ = s2u(Bs + buf * 32 * BPITCH);
        int k0 = c * 32;
#pragma unroll
        for (int i = tid; i < 1024; i += 512) {
            int row = i >> 3, seg = i & 7;
            cpa16(au + (uint32_t)(row * APITCH + seg * 4) * 4,
                  Ab + (size_t)row * II + k0 + seg * 4);
        }
#pragma unroll
        for (int i = tid; i < 2048; i += 512) {
            int k = i >> 6, seg = i & 63;
            cpa16(bu_ + (uint32_t)(k * BPITCH + seg * 4) * 4,
                  Bb + (size_t)(k0 + k) * HH + seg * 4);
        }
    };

    fill(0, 0); cpa_commit();
    float acc[4][4][4] = {};
    const int NC = II / 32; // 48
    for (int c = 0; c < NC; c++) {
        int b = c & 1;
        if (c + 1 < NC) { fill(b ^ 1, c + 1); cpa_commit(); cpa_wait<1>(); }
        else { cpa_wait<0>(); }
        __syncthreads();
        const float* A = As + b * 128 * APITCH;
        const float* B = Bs + b * 32 * BPITCH;
#pragma unroll
        for (int ks = 0; ks < 4; ks++) {
            int kc = ks * 8 + (lane & 3);
            int r0 = warpM * 64 + (lane >> 2);
            uint32_t af[4][4];
#pragma unroll
            for (int mf = 0; mf < 4; mf++) {
                int r = r0 + mf * 16;
                af[mf][0] = f2tf(A[r * APITCH + kc]);
                af[mf][1] = f2tf(A[(r + 8) * APITCH + kc]);
                af[mf][2] = f2tf(A[r * APITCH + kc + 4]);
                af[mf][3] = f2tf(A[(r + 8) * APITCH + kc + 4]);
            }
            int bn = warpN * 32 + (lane >> 2);
            uint32_t bf[4][2];
#pragma unroll
            for (int nf = 0; nf < 4; nf++) {
                bf[nf][0] = f2tf(B[kc * BPITCH + bn + nf * 8]);
                bf[nf][1] = f2tf(B[(kc + 4) * BPITCH + bn + nf * 8]);
            }
#pragma unroll
            for (int mf = 0; mf < 4; mf++)
#pragma unroll
                for (int nf = 0; nf < 4; nf++)
                    mma8(acc[mf][nf], af[mf], bf[nf]);
        }
        __syncthreads();
    }

#pragma unroll
    for (int mf = 0; mf < 4; mf++) {
        int rbase = warpM * 64 + mf * 16 + (lane >> 2);
#pragma unroll
        for (int nf = 0; nf < 4; nf++) {
            int col = bx * 256 + warpN * 32 + nf * 8 + 2 * (lane & 3);
#pragma unroll
            for (int h = 0; h < 2; h++) {
                int r = rbase + h * 8;
                if (r < valid) {
                    float2 o;
                    o.x = acc[mf][nf][h * 2 + 0];
                    o.y = acc[mf][nf][h * 2 + 1];
                    *(float2*)&g_ybuf[((size_t)e * SLOTS + slot0 + r) * HH + col] = o;
                }
            }
        }
    }
}

// ---------------- combine ----------------
__global__ void combine_kernel(float* __restrict__ out) {
    int t = blockIdx.x;
    __shared__ int se[2], ss[2];
    __shared__ float sw[2];
    if (threadIdx.x < 2) {
        se[threadIdx.x] = g_topk_idx[t * 2 + threadIdx.x];
        ss[threadIdx.x] = g_slot[t * 2 + threadIdx.x];
        sw[threadIdx.x] = g_topk_w[t * 2 + threadIdx.x];
    }
    __syncthreads();
    for (int h = threadIdx.x; h < HH; h += 256) {
        float v = 0.0f;
        if (ss[0] >= 0) v += sw[0] * g_ybuf[((size_t)se[0] * SLOTS + ss[0]) * HH + h];
        if (ss[1] >= 0) v += sw[1] * g_ybuf[((size_t)se[1] * SLOTS + ss[1]) * HH + h];
        out[(size_t)t * HH + h] = v;
    }
}

// ---------------- aux ----------------
__global__ void aux_kernel(float* __restrict__ out, int out_size) {
    if (out_size < TT * HH + 1) return;
    float a = 0.0f;
    for (int e = 0; e < EE; e++) {
        float usage = (float)g_keptcnt[e] / (float)(TT * KK);
        float imp = g_importance[e] / (float)TT;
        a += usage * imp;
    }
    a *= (float)EE;
    if (g_dropped > 0.0f) a += g_dropped / (float)TT * 0.1f;
    a = fminf(a, 1.0f) * 0.001f;
    out[TT * HH] = a;
}

// ---------------- launch ----------------
extern "C" void kernel_launch(void* const* d_in, const int* in_sizes, int n_in,
                              void* d_out, int out_size) {
    const float* x      = (const float*)d_in[0];
    const float* w_gate = (const float*)d_in[1];
    const float* w1     = (const float*)d_in[2];
    const float* w3     = (const float*)d_in[3];
    const float* w2     = (const float*)d_in[4];
    float* out = (float*)d_out;

    cudaFuncSetAttribute(gemm1_mma, cudaFuncAttributeMaxDynamicSharedMemorySize, G1_SMEM);
    cudaFuncSetAttribute(gemm2_mma, cudaFuncAttributeMaxDynamicSharedMemorySize, G2_SMEM);

    zero_kernel<<<1, 32>>>();
    routing_kernel<<<TT, 256>>>(x, w_gate);
    scan_kernel<<<1, 1024>>>();
    gemm1_mma<<<dim3(II / 128, SLOTS / 128, EE), 512, G1_SMEM>>>(x, w1, w3);
    gemm2_mma<<<dim3(HH / 256, SLOTS / 128, EE), 512, G2_SMEM>>>(w2);
    combine_kernel<<<TT, 256>>>(out);
    aux_kernel<<<1, 1>>>(out, out_size);
}